// round 13
// baseline (speedup 1.0000x reference)
#include <cuda_runtime.h>
#include <cuda_fp16.h>
#include <cstdint>

#define Bq 8
#define Hq 128
#define Wq 128
#define Cq 128
#define Fq 128

// fp16 copy of x (NHWC), 32 MB scratch
__device__ __half g_xhalf[(size_t)Bq * Hq * Wq * Cq];
// fp16 modulated+demodulated weights: slab per (b,tap,cc): [f][kk] (128 x 32 halves)
__device__ __half g_wmodh[(size_t)Bq * 9 * Cq * Fq];

// ---------------------------------------------------------------------------
// x -> fp16 pre-pass
// ---------------------------------------------------------------------------
__global__ __launch_bounds__(256) void xconv_kernel(const float* __restrict__ x)
{
    size_t i = ((size_t)blockIdx.x * 256 + threadIdx.x) * 4;
    float4 v = *(const float4*)(x + i);
    __half2 h0 = __float22half2_rn(make_float2(v.x, v.y));
    __half2 h1 = __float22half2_rn(make_float2(v.z, v.w));
    uint2 o;
    o.x = *(uint32_t*)&h0;
    o.y = *(uint32_t*)&h1;
    *(uint2*)(g_xhalf + i) = o;
}

// ---------------------------------------------------------------------------
// Modulate + demodulate weights -> fp16
// ---------------------------------------------------------------------------
__global__ __launch_bounds__(256) void modw_kernel(const float* __restrict__ style,
                                                   const float* __restrict__ kern)
{
    const int fg = blockIdx.x;
    const int b  = blockIdx.y;
    const int f0 = fg * 32;
    const int tid = threadIdx.x;
    const int fi = tid & 31;
    const int cp = tid >> 5;

    __shared__ float ssty[Cq];
    __shared__ float red[8][32];
    __shared__ float rr[32];

    if (tid < Cq) ssty[tid] = style[b * Cq + tid] + 1.0f;
    __syncthreads();

    float sq = 0.0f;
    for (int k = 0; k < 9; k++) {
#pragma unroll 4
        for (int j = 0; j < 16; j++) {
            int c = cp + j * 8;
            float kv = kern[(k * Cq + c) * Fq + f0 + fi] * ssty[c];
            sq += kv * kv;
        }
    }
    red[cp][fi] = sq;
    __syncthreads();
    if (tid < 32) {
        float t = 0.0f;
#pragma unroll
        for (int j = 0; j < 8; j++) t += red[j][tid];
        float xarg = t + 1e-8f;
        float r = rsqrtf(xarg);
        r = r * (1.5f - 0.5f * xarg * r * r);
        rr[tid] = r;
    }
    __syncthreads();

    for (int i = tid; i < 9 * Cq * 32; i += 256) {
        int k   = i >> 12;
        int rem = i & 4095;
        int c   = rem >> 5;
        int fl  = rem & 31;
        float v = kern[(k * Cq + c) * Fq + f0 + fl] * ssty[c] * rr[fl];
        g_wmodh[((((size_t)(b * 9 + k) * 4 + (c >> 5)) * 128) + (f0 + fl)) * 32 + (c & 31)] =
            __float2half_rn(v);
    }
}

// ---------------------------------------------------------------------------
// Conv kernel: CTA = (b, output row h0). GEMM M=128(w) x N=128(f), K=1152.
// mma.sync.m16n8k16 fp16 -> fp32.  8 warps = 4(m) x 2(n), warp tile 32x64.
// Padded-row smem (20 words = 16 data + 4 pad), no XOR swizzle.
// Band single-buffered, ws triple-buffered. 61.9 KB smem -> 2 CTAs/SM.
// ---------------------------------------------------------------------------
#define ROWW 20                         // words per 32-half row (16 + 4 pad)
#define XS_WORDS (3 * 130 * ROWW)       // 7800
#define WS_WORDS (128 * ROWW)           // 2560
#define SMEM_WORDS (XS_WORDS + 3 * WS_WORDS)
#define SMEM_BYTES (SMEM_WORDS * 4)     // 61920

#define NTHREADS 256

__device__ __forceinline__ void cp_async16(uint32_t daddr, const void* saddr, int srcsz) {
    asm volatile("cp.async.cg.shared.global [%0], [%1], 16, %2;"
                 :: "r"(daddr), "l"(saddr), "r"(srcsz) : "memory");
}
__device__ __forceinline__ void cp_commit() {
    asm volatile("cp.async.commit_group;" ::: "memory");
}
__device__ __forceinline__ void cp_wait0() {
    asm volatile("cp.async.wait_group 0;" ::: "memory");
}

__device__ __forceinline__ void mma_f16(float& c0, float& c1, float& c2, float& c3,
                                        uint32_t a0, uint32_t a1, uint32_t a2, uint32_t a3,
                                        uint32_t b0, uint32_t b1) {
    asm volatile("mma.sync.aligned.m16n8k16.row.col.f32.f16.f16.f32 "
                 "{%0,%1,%2,%3}, {%4,%5,%6,%7}, {%8,%9}, {%0,%1,%2,%3};"
                 : "+f"(c0), "+f"(c1), "+f"(c2), "+f"(c3)
                 : "r"(a0), "r"(a1), "r"(a2), "r"(a3), "r"(b0), "r"(b1));
}

__global__ __launch_bounds__(NTHREADS, 2) void conv_tc_kernel(float* __restrict__ out)
{
    extern __shared__ uint32_t smu[];
    uint32_t smbase;
    asm("{ .reg .u64 t; cvta.to.shared.u64 t, %1; cvt.u32.u64 %0, t; }"
        : "=r"(smbase) : "l"(smu));

    const int tid = threadIdx.x;
    const int lane = tid & 31;
    const int wid  = tid >> 5;
    const int g    = lane >> 2;       // groupID (0..7)
    const int tig  = lane & 3;        // thread-in-group
    const int warpM = wid & 3;        // 0..3 (m tiles of 32)
    const int warpN = wid >> 2;       // 0..1 (n tiles of 64)

    const int h0 = blockIdx.x;
    const int b  = blockIdx.y;

    float acc[2][8][4];
#pragma unroll
    for (int mt = 0; mt < 2; mt++)
#pragma unroll
        for (int nt = 0; nt < 8; nt++)
#pragma unroll
            for (int q = 0; q < 4; q++) acc[mt][nt][q] = 0.0f;

    // x band for c-chunk cc: band[r][p] = 32 halves at word (r*130+p)*ROWW
    auto fill_band = [&](int cc) {
        const __half* xb = g_xhalf + ((size_t)b * Hq) * Wq * Cq + cc * 32;
        for (int i = tid; i < 3 * 130 * 4; i += NTHREADS) {
            int r   = i / 520;
            int rem = i - r * 520;
            int p   = rem >> 2;
            int j   = rem & 3;          // 16B chunk (8 halves)
            int gh = h0 - 1 + r;
            int gw = p - 1;
            int valid = (gh >= 0 && gh < Hq && gw >= 0 && gw < Wq) ? 16 : 0;
            int ghc = gh < 0 ? 0 : (gh > Hq - 1 ? Hq - 1 : gh);
            int gwc = gw < 0 ? 0 : (gw > Wq - 1 ? Wq - 1 : gw);
            const __half* src = xb + ((size_t)ghc * Wq + gwc) * Cq + j * 8;
            uint32_t w = (r * 130 + p) * ROWW + j * 4;
            cp_async16(smbase + w * 4, src, valid);
        }
    };
    // weight slab (b,tap,cc) into ws buffer bb (of 3): row f = 32 halves
    auto fill_ws = [&](int tap, int cc, int bb) {
        const __half* src0 = g_wmodh + (((size_t)(b * 9 + tap) * 4 + cc)) * (128 * 32);
        for (int i = tid; i < 512; i += NTHREADS) {
            int f = i >> 2;
            int j = i & 3;
            uint32_t w = XS_WORDS + bb * WS_WORDS + f * ROWW + j * 4;
            cp_async16(smbase + w * 4, src0 + f * 32 + j * 8, 16);
        }
    };

    // ---- prologue ----
    fill_band(0);
    fill_ws(0, 0, 0);
    cp_commit();

    for (int it = 0; it < 36; it++) {
        const int cc  = it / 9;
        const int tap = it - cc * 9;
        const int kh = tap / 3;
        const int kw = tap - kh * 3;

        cp_wait0();
        __syncthreads();

        if (tap == 0 && cc > 0) {
            fill_band(cc);
            if (it + 1 < 36) fill_ws((it + 1) % 9, (it + 1) / 9, (it + 1) % 3);
            cp_commit();
            cp_wait0();             // band needed THIS iter (3x, small exposed cost)
            __syncthreads();
        } else {
            if (it + 1 < 36) fill_ws((it + 1) % 9, (it + 1) / 9, (it + 1) % 3);
            cp_commit();
        }

        const int xb = kh * 130 * ROWW;
        const int wb = XS_WORDS + (it % 3) * WS_WORDS;

        const int mA = warpM * 32 + g;
        const int pA0 = mA + kw;            // mt0 rows g, g+8
        const int pA1 = pA0 + 8;
        const int pB0 = pA0 + 16;           // mt1 rows
        const int pB1 = pA0 + 24;
        const int baseA0 = xb + pA0 * ROWW + tig;
        const int baseA1 = xb + pA1 * ROWW + tig;
        const int baseB0 = xb + pB0 * ROWW + tig;
        const int baseB1 = xb + pB1 * ROWW + tig;
        const int fbase  = wb + (warpN * 64 + g) * ROWW + tig;

#pragma unroll
        for (int ks = 0; ks < 2; ks++) {
            const int ko = ks * 8;
            uint32_t a0[2], a1[2], a2[2], a3[2];
            a0[0] = smu[baseA0 + ko];
            a2[0] = smu[baseA0 + ko + 4];
            a1[0] = smu[baseA1 + ko];
            a3[0] = smu[baseA1 + ko + 4];
            a0[1] = smu[baseB0 + ko];
            a2[1] = smu[baseB0 + ko + 4];
            a1[1] = smu[baseB1 + ko];
            a3[1] = smu[baseB1 + ko + 4];

#pragma unroll
            for (int nt = 0; nt < 8; nt++) {
                const int bw = fbase + nt * 8 * ROWW + ko;
                uint32_t b0 = smu[bw];
                uint32_t b1 = smu[bw + 4];
                mma_f16(acc[0][nt][0], acc[0][nt][1], acc[0][nt][2], acc[0][nt][3],
                        a0[0], a1[0], a2[0], a3[0], b0, b1);
                mma_f16(acc[1][nt][0], acc[1][nt][1], acc[1][nt][2], acc[1][nt][3],
                        a0[1], a1[1], a2[1], a3[1], b0, b1);
            }
        }
    }

    // ---- epilogue: direct STG from accumulators ----
    float* ob = out + (((size_t)b * Hq + h0) * Wq) * Fq;
#pragma unroll
    for (int mt = 0; mt < 2; mt++) {
        const int m = warpM * 32 + mt * 16 + g;
#pragma unroll
        for (int nt = 0; nt < 8; nt++) {
            const int f = warpN * 64 + nt * 8 + tig * 2;
            float2 v0 = make_float2(acc[mt][nt][0], acc[mt][nt][1]);
            float2 v1 = make_float2(acc[mt][nt][2], acc[mt][nt][3]);
            *(float2*)(ob + (size_t)m * Fq + f) = v0;
            *(float2*)(ob + (size_t)(m + 8) * Fq + f) = v1;
        }
    }
}

// ---------------------------------------------------------------------------
extern "C" void kernel_launch(void* const* d_in, const int* in_sizes, int n_in,
                              void* d_out, int out_size)
{
    const float* x     = (const float*)d_in[0];   // (8,128,128,128) NHWC
    const float* style = (const float*)d_in[1];   // (8,128)
    const float* kern  = (const float*)d_in[2];   // (3,3,128,128)
    float* out = (float*)d_out;

    (void)in_sizes; (void)n_in; (void)out_size;

    cudaFuncSetAttribute(conv_tc_kernel, cudaFuncAttributeMaxDynamicSharedMemorySize, SMEM_BYTES);

    xconv_kernel<<<(Bq * Hq * Wq * Cq) / (256 * 4), 256>>>(x);

    dim3 gridM(4, Bq);
    modw_kernel<<<gridM, 256>>>(style, kern);

    dim3 gridC(Hq, Bq);                            // 128 rows x 8 batch = 1024 CTAs
    conv_tc_kernel<<<gridC, NTHREADS, SMEM_BYTES>>>(out);
}

// round 16
// speedup vs baseline: 1.1612x; 1.1612x over previous
#include <cuda_runtime.h>
#include <cstdint>

#define Bq 8
#define Hq 128
#define Wq 128
#define Cq 128
#define Fq 128

// ---------------------------------------------------------------------------
// Modulated+demodulated weights, vector-load layout:
// slab per (b,tap,cc): 128 f-rows, row stride 36 words (32 data + 4 pad),
// within-row k' = (k%4)*8 + k/4  (so thread tig's 8 words are [tig*8, tig*8+8)).
// Values pre-rounded to tf32 (cvt.rna).
// ---------------------------------------------------------------------------
#define WSLAB 4608                     // words per slab: 128 * 36
__device__ float g_wmod[(size_t)Bq * 9 * 4 * WSLAB];

__global__ __launch_bounds__(256) void modw_kernel(const float* __restrict__ style,
                                                   const float* __restrict__ kern)
{
    const int fg = blockIdx.x;
    const int b  = blockIdx.y;
    const int f0 = fg * 32;
    const int tid = threadIdx.x;
    const int fi = tid & 31;
    const int cp = tid >> 5;

    __shared__ float ssty[Cq];
    __shared__ float red[8][32];
    __shared__ float rr[32];

    if (tid < Cq) ssty[tid] = style[b * Cq + tid] + 1.0f;
    __syncthreads();

    float sq = 0.0f;
    for (int k = 0; k < 9; k++) {
#pragma unroll 4
        for (int j = 0; j < 16; j++) {
            int c = cp + j * 8;
            float kv = kern[(k * Cq + c) * Fq + f0 + fi] * ssty[c];
            sq += kv * kv;
        }
    }
    red[cp][fi] = sq;
    __syncthreads();
    if (tid < 32) {
        float t = 0.0f;
#pragma unroll
        for (int j = 0; j < 8; j++) t += red[j][tid];
        float xarg = t + 1e-8f;
        float r = rsqrtf(xarg);
        r = r * (1.5f - 0.5f * xarg * r * r);
        rr[tid] = r;
    }
    __syncthreads();

    // zero pad words (32..35) of this f-group's rows across all 36 slabs
    for (int i = tid; i < 9 * 4 * 32 * 4; i += 256) {
        int slab = i >> 7;              // 9*4 slabs
        int rem  = i & 127;
        int fl   = rem >> 2;
        int pw   = rem & 3;
        g_wmod[((size_t)(b * 36) + slab) * WSLAB + (f0 + fl) * 36 + 32 + pw] = 0.0f;
    }

    for (int i = tid; i < 9 * Cq * 32; i += 256) {
        int k   = i >> 12;
        int rem = i & 4095;
        int c   = rem >> 5;
        int fl  = rem & 31;
        float v = kern[(k * Cq + c) * Fq + f0 + fl] * ssty[c] * rr[fl];
        uint32_t bits;
        asm("cvt.rna.tf32.f32 %0, %1;" : "=r"(bits) : "f"(v));
        int kk = c & 31;
        int kp = (kk & 3) * 8 + (kk >> 2);
        g_wmod[((size_t)(b * 9 + k) * 4 + (c >> 5)) * WSLAB + (f0 + fl) * 36 + kp] =
            __uint_as_float(bits);
    }
}

// ---------------------------------------------------------------------------
// Conv kernel: CTA = (b, output row h0). GEMM M=128(w) x N=128(f), K=1152.
// mma.sync.m16n8k8 tf32.  8 warps = 4(m) x 2(n), warp tile 32x64.
// A: scalar LDS from XOR-swizzled band (as R11).
// B: two LDS.128 per f-row cover all 4 k-steps (k-permuted slab).
// Band single-buffered, ws triple-buffered. 105216 B smem -> 2 CTAs/SM.
// ---------------------------------------------------------------------------
#define XS_WORDS 12480                 // 3 rows * 130 pos * 32 c floats
#define WS_WORDS WSLAB                 // 4608
#define SMEM_WORDS (XS_WORDS + 3 * WS_WORDS)
#define SMEM_BYTES (SMEM_WORDS * 4)    // 105216

#define NTHREADS 256

__device__ __forceinline__ void cp_async16(uint32_t daddr, const void* saddr, int srcsz) {
    asm volatile("cp.async.cg.shared.global [%0], [%1], 16, %2;"
                 :: "r"(daddr), "l"(saddr), "r"(srcsz) : "memory");
}
__device__ __forceinline__ void cp_commit() {
    asm volatile("cp.async.commit_group;" ::: "memory");
}
__device__ __forceinline__ void cp_wait0() {
    asm volatile("cp.async.wait_group 0;" ::: "memory");
}

__device__ __forceinline__ void mma_tf32(float& c0, float& c1, float& c2, float& c3,
                                         uint32_t a0, uint32_t a1, uint32_t a2, uint32_t a3,
                                         uint32_t b0, uint32_t b1) {
    asm volatile("mma.sync.aligned.m16n8k8.row.col.f32.tf32.tf32.f32 "
                 "{%0,%1,%2,%3}, {%4,%5,%6,%7}, {%8,%9}, {%0,%1,%2,%3};"
                 : "+f"(c0), "+f"(c1), "+f"(c2), "+f"(c3)
                 : "r"(a0), "r"(a1), "r"(a2), "r"(a3), "r"(b0), "r"(b1));
}

__global__ __launch_bounds__(NTHREADS, 2) void conv_tc_kernel(const float* __restrict__ x,
                                                              float* __restrict__ out)
{
    extern __shared__ float sm[];
    uint32_t smbase;
    asm("{ .reg .u64 t; cvta.to.shared.u64 t, %1; cvt.u32.u64 %0, t; }"
        : "=r"(smbase) : "l"(sm));

    const int tid = threadIdx.x;
    const int lane = tid & 31;
    const int wid  = tid >> 5;
    const int g    = lane >> 2;       // groupID (0..7)
    const int tig  = lane & 3;        // thread-in-group
    const int warpM = wid & 3;        // 0..3 (m tiles of 32)
    const int warpN = wid >> 2;       // 0..1 (n tiles of 64)

    const int h0 = blockIdx.x;
    const int b  = blockIdx.y;

    float acc[2][8][4];
#pragma unroll
    for (int mt = 0; mt < 2; mt++)
#pragma unroll
        for (int nt = 0; nt < 8; nt++)
#pragma unroll
            for (int q = 0; q < 4; q++) acc[mt][nt][q] = 0.0f;

    // x band for c-chunk cc (single buffer): xs[r][p][kk], word swizzle kk ^ ((p&7)*4)
    auto fill_band = [&](int cc) {
        const float* xb = x + ((size_t)b * Hq) * Wq * Cq + cc * 32;
        for (int i = tid; i < 3 * 130 * 8; i += NTHREADS) {
            int r   = i / 1040;
            int rem = i - r * 1040;
            int p   = rem >> 3;
            int kk4 = rem & 7;
            int gh = h0 - 1 + r;
            int gw = p - 1;
            int valid = (gh >= 0 && gh < Hq && gw >= 0 && gw < Wq) ? 16 : 0;
            int ghc = gh < 0 ? 0 : (gh > Hq - 1 ? Hq - 1 : gh);
            int gwc = gw < 0 ? 0 : (gw > Wq - 1 ? Wq - 1 : gw);
            const float* src = xb + ((size_t)ghc * Wq + gwc) * Cq + kk4 * 4;
            uint32_t w = (r * 130 + p) * 32 + ((kk4 * 4) ^ ((p & 7) * 4));
            cp_async16(smbase + w * 4, src, valid);
        }
    };
    // weight slab (b,tap,cc) -> ws buffer bb: straight linear 18KB copy
    auto fill_ws = [&](int tap, int cc, int bb) {
        const float* src0 = g_wmod + ((size_t)(b * 9 + tap) * 4 + cc) * WSLAB;
        for (int i = tid; i < WSLAB / 4; i += NTHREADS) {
            uint32_t w = XS_WORDS + bb * WS_WORDS + i * 4;
            cp_async16(smbase + w * 4, src0 + i * 4, 16);
        }
    };

    // ---- prologue ----
    fill_band(0);
    fill_ws(0, 0, 0);
    cp_commit();

    for (int it = 0; it < 36; it++) {
        const int cc  = it / 9;
        const int tap = it - cc * 9;
        const int kh = tap / 3;
        const int kw = tap - kh * 3;

        cp_wait0();                 // data for iter it arrived
        __syncthreads();            // all warps done reading iter it-1 buffers

        if (tap == 0 && cc > 0) {
            fill_band(cc);
            if (it + 1 < 36) fill_ws((it + 1) % 9, (it + 1) / 9, (it + 1) % 3);
            cp_commit();
            cp_wait0();             // band needed THIS iter (3x, small exposed cost)
            __syncthreads();
        } else {
            if (it + 1 < 36) fill_ws((it + 1) % 9, (it + 1) / 9, (it + 1) % 3);
            cp_commit();
        }

        const int xb = kh * 130 * 32;
        const int wb = XS_WORDS + (it % 3) * WS_WORDS;

        const int mA = warpM * 32 + g;
        const int pA0 = mA + kw,  pA1 = pA0 + 8;
        const int pB0 = pA0 + 16, pB1 = pA0 + 24;
        const int baseA0 = xb + pA0 * 32, mkA0 = (pA0 & 7) * 4;
        const int baseA1 = xb + pA1 * 32, mkA1 = (pA1 & 7) * 4;
        const int baseB0 = xb + pB0 * 32, mkB0 = (pB0 & 7) * 4;
        const int baseB1 = xb + pB1 * 32, mkB1 = (pB1 & 7) * 4;

        // ---- preload ALL A fragments for the 4 k-steps (32 regs) ----
        uint32_t A0[4][4], A1[4][4];   // [ks][a0,a1,a2,a3] for mt0 / mt1
#pragma unroll
        for (int ks = 0; ks < 4; ks++) {
            const int k0 = ks * 8 + tig;
            A0[ks][0] = __float_as_uint(sm[baseA0 + (k0 ^ mkA0)]);
            A0[ks][2] = __float_as_uint(sm[baseA0 + ((k0 + 4) ^ mkA0)]);
            A0[ks][1] = __float_as_uint(sm[baseA1 + (k0 ^ mkA1)]);
            A0[ks][3] = __float_as_uint(sm[baseA1 + ((k0 + 4) ^ mkA1)]);
            A1[ks][0] = __float_as_uint(sm[baseB0 + (k0 ^ mkB0)]);
            A1[ks][2] = __float_as_uint(sm[baseB0 + ((k0 + 4) ^ mkB0)]);
            A1[ks][1] = __float_as_uint(sm[baseB1 + (k0 ^ mkB1)]);
            A1[ks][3] = __float_as_uint(sm[baseB1 + ((k0 + 4) ^ mkB1)]);
        }

        // ---- B: per f-row, two LDS.128 cover all 4 k-steps ----
        const int fbase = wb + (warpN * 64 + g) * 36 + tig * 8;
#pragma unroll
        for (int nt = 0; nt < 8; nt++) {
            const int frow = fbase + nt * 8 * 36;
            float4 w0 = *(const float4*)&sm[frow];
            float4 w1 = *(const float4*)&sm[frow + 4];
            uint32_t bw[8];
            bw[0] = __float_as_uint(w0.x); bw[1] = __float_as_uint(w0.y);
            bw[2] = __float_as_uint(w0.z); bw[3] = __float_as_uint(w0.w);
            bw[4] = __float_as_uint(w1.x); bw[5] = __float_as_uint(w1.y);
            bw[6] = __float_as_uint(w1.z); bw[7] = __float_as_uint(w1.w);
#pragma unroll
            for (int ks = 0; ks < 4; ks++) {
                mma_tf32(acc[0][nt][0], acc[0][nt][1], acc[0][nt][2], acc[0][nt][3],
                         A0[ks][0], A0[ks][1], A0[ks][2], A0[ks][3],
                         bw[2 * ks], bw[2 * ks + 1]);
                mma_tf32(acc[1][nt][0], acc[1][nt][1], acc[1][nt][2], acc[1][nt][3],
                         A1[ks][0], A1[ks][1], A1[ks][2], A1[ks][3],
                         bw[2 * ks], bw[2 * ks + 1]);
            }
        }
    }

    // ---- epilogue: direct STG from accumulators ----
    float* ob = out + (((size_t)b * Hq + h0) * Wq) * Fq;
#pragma unroll
    for (int mt = 0; mt < 2; mt++) {
        const int m = warpM * 32 + mt * 16 + g;
#pragma unroll
        for (int nt = 0; nt < 8; nt++) {
            const int f = warpN * 64 + nt * 8 + tig * 2;
            float2 v0 = make_float2(acc[mt][nt][0], acc[mt][nt][1]);
            float2 v1 = make_float2(acc[mt][nt][2], acc[mt][nt][3]);
            *(float2*)(ob + (size_t)m * Fq + f) = v0;
            *(float2*)(ob + (size_t)(m + 8) * Fq + f) = v1;
        }
    }
}

// ---------------------------------------------------------------------------
extern "C" void kernel_launch(void* const* d_in, const int* in_sizes, int n_in,
                              void* d_out, int out_size)
{
    const float* x     = (const float*)d_in[0];   // (8,128,128,128) NHWC
    const float* style = (const float*)d_in[1];   // (8,128)
    const float* kern  = (const float*)d_in[2];   // (3,3,128,128)
    float* out = (float*)d_out;

    (void)in_sizes; (void)n_in; (void)out_size;

    cudaFuncSetAttribute(conv_tc_kernel, cudaFuncAttributeMaxDynamicSharedMemorySize, SMEM_BYTES);

    dim3 gridM(4, Bq);
    modw_kernel<<<gridM, 256>>>(style, kern);

    dim3 gridC(Hq, Bq);                            // 128 rows x 8 batch = 1024 CTAs
    conv_tc_kernel<<<gridC, NTHREADS, SMEM_BYTES>>>(x, out);
}